// round 3
// baseline (speedup 1.0000x reference)
#include <cuda_runtime.h>
#include <cuda_bf16.h>
#include <cstdint>
#include <math.h>

#define Bn 32
#define Tn 2048
#define Dn 512
#define ZB 32
#define SPLIT 32          // one batch per split-K chunk
#define SEG 8
#define NIT (Tn / 32)     // gram k-iterations (BK=32)

// ---------------- static scratch ----------------
__device__ float g_pmean[SEG][Bn][Dn];
__device__ float g_bmean[Bn][Dn];
__device__ float g_gmean[Dn];
__device__ __nv_bfloat16 g_xcb[(size_t)Bn * Tn * Dn];   // bf16 copy of x (uncentered)
__device__ float g_Gpart[SPLIT][Dn * Dn];               // split-K Gram partials
__device__ float g_C[Dn * Dn];                          // covariance -> Cholesky (lower)

__device__ __forceinline__ uint32_t smem_u32(const void* p) {
    return (uint32_t)__cvta_generic_to_shared(p);
}

// ---------------- 1) fused: partial means + bf16 convert --------------------
__global__ void conv_mean(const float* __restrict__ x) {
    int b   = blockIdx.y;
    int seg = blockIdx.z;
    int d   = blockIdx.x * 128 + threadIdx.x;
    size_t base = ((size_t)b * Tn + (size_t)seg * (Tn / SEG)) * Dn + d;
    float s = 0.f;
#pragma unroll 4
    for (int t = 0; t < Tn / SEG; t++) {
        float f = x[base + (size_t)t * Dn];
        s += f;
        g_xcb[base + (size_t)t * Dn] = __float2bfloat16_rn(f);
    }
    g_pmean[seg][b][d] = s;
}

__global__ void mean_final() {
    int idx = blockIdx.x * 256 + threadIdx.x;
    if (idx >= Bn * Dn) return;
    int b = idx / Dn, d = idx % Dn;
    float s = 0.f;
#pragma unroll
    for (int g = 0; g < SEG; g++) s += g_pmean[g][b][d];
    g_bmean[b][d] = s * (1.0f / (float)Tn);
}

__global__ void gmean_kernel() {
    int d = threadIdx.x;
    float s = 0.f;
#pragma unroll
    for (int b = 0; b < Bn; b++) s += g_bmean[b][d];
    g_gmean[d] = s * (1.0f / (float)Bn);
}

// ---------------- 2) tensor-core Gram: G = sum_{b,t} x x^T ------------------
// grid (4,4,32): 128x128 output tile (lower tiles only), K-chunk = one batch.
// 256 threads = 8 warps (2x4), each warp 64m x 32n via mma.m16n8k16 bf16.
__global__ void __launch_bounds__(256) gram_mma(const __nv_bfloat16* __restrict__ xb) {
    if (blockIdx.y > blockIdx.x) return;
    int dtile = blockIdx.x * 128;
    int etile = blockIdx.y * 128;
    int bz    = blockIdx.z;

    __shared__ __nv_bfloat16 As[2][32][128];   // [stage][k][d]
    __shared__ __nv_bfloat16 Bs[2][32][128];   // [stage][k][e]

    int tid  = threadIdx.x;
    int lane = tid & 31;
    int warp = tid >> 5;
    int m0 = (warp >> 2) * 64;
    int n0 = (warp & 3) * 32;

    const __nv_bfloat16* xbase = xb + (size_t)bz * Tn * Dn;

    float acc[4][4][4];
#pragma unroll
    for (int a = 0; a < 4; a++)
#pragma unroll
        for (int b = 0; b < 4; b++)
#pragma unroll
            for (int c = 0; c < 4; c++) acc[a][b][c] = 0.f;

    // loader: 2 chunks (16B) per thread per tile per stage
    auto issue = [&](int it, int stg) {
#pragma unroll
        for (int rep = 0; rep < 2; rep++) {
            int l    = tid + rep * 256;
            int row  = l >> 4;         // 0..31
            int ch   = l & 15;         // 16B chunk
            int chs  = ch ^ (row & 7); // xor swizzle
            const __nv_bfloat16* gA = xbase + (size_t)(it * 32 + row) * Dn + dtile + ch * 8;
            const __nv_bfloat16* gB = xbase + (size_t)(it * 32 + row) * Dn + etile + ch * 8;
            uint32_t sA = smem_u32(&As[stg][row][chs * 8]);
            uint32_t sB = smem_u32(&Bs[stg][row][chs * 8]);
            asm volatile("cp.async.cg.shared.global [%0], [%1], 16;" :: "r"(sA), "l"(gA));
            asm volatile("cp.async.cg.shared.global [%0], [%1], 16;" :: "r"(sB), "l"(gB));
        }
    };

    issue(0, 0);
    asm volatile("cp.async.commit_group;");

    for (int it = 0; it < NIT; it++) {
        if (it + 1 < NIT) {
            issue(it + 1, (it + 1) & 1);
            asm volatile("cp.async.commit_group;");
            asm volatile("cp.async.wait_group 1;");
        } else {
            asm volatile("cp.async.wait_group 0;");
        }
        __syncthreads();
        int stg = it & 1;

#pragma unroll
        for (int ks = 0; ks < 2; ks++) {
            uint32_t a[4][4];
            uint32_t bfr[2][4];
#pragma unroll
            for (int mi = 0; mi < 4; mi++) {
                int krow = ks * 16 + (lane & 7) + ((lane & 16) ? 8 : 0);
                int ch   = (m0 >> 3) + mi * 2 + ((lane >> 3) & 1);
                int chs  = ch ^ (krow & 7);
                uint32_t addr = smem_u32(&As[stg][krow][chs * 8]);
                asm volatile("ldmatrix.sync.aligned.m8n8.x4.trans.shared.b16 {%0,%1,%2,%3}, [%4];"
                             : "=r"(a[mi][0]), "=r"(a[mi][1]), "=r"(a[mi][2]), "=r"(a[mi][3])
                             : "r"(addr));
            }
#pragma unroll
            for (int pb = 0; pb < 2; pb++) {
                int krow = ks * 16 + (lane & 7) + ((lane & 8) ? 8 : 0);
                int ch   = (n0 >> 3) + pb * 2 + ((lane >> 4) & 1);
                int chs  = ch ^ (krow & 7);
                uint32_t addr = smem_u32(&Bs[stg][krow][chs * 8]);
                asm volatile("ldmatrix.sync.aligned.m8n8.x4.trans.shared.b16 {%0,%1,%2,%3}, [%4];"
                             : "=r"(bfr[pb][0]), "=r"(bfr[pb][1]), "=r"(bfr[pb][2]), "=r"(bfr[pb][3])
                             : "r"(addr));
            }
#pragma unroll
            for (int mi = 0; mi < 4; mi++)
#pragma unroll
                for (int nb = 0; nb < 4; nb++) {
                    uint32_t b0 = bfr[nb >> 1][(nb & 1) * 2];
                    uint32_t b1 = bfr[nb >> 1][(nb & 1) * 2 + 1];
                    asm volatile(
                        "mma.sync.aligned.m16n8k16.row.col.f32.bf16.bf16.f32 "
                        "{%0,%1,%2,%3}, {%4,%5,%6,%7}, {%8,%9}, {%0,%1,%2,%3};"
                        : "+f"(acc[mi][nb][0]), "+f"(acc[mi][nb][1]),
                          "+f"(acc[mi][nb][2]), "+f"(acc[mi][nb][3])
                        : "r"(a[mi][0]), "r"(a[mi][1]), "r"(a[mi][2]), "r"(a[mi][3]),
                          "r"(b0), "r"(b1));
                }
        }
        __syncthreads();
    }

    // epilogue: write fp32 partials
    float* gp = g_Gpart[bz];
    int g  = lane >> 2;
    int tg = lane & 3;
#pragma unroll
    for (int mi = 0; mi < 4; mi++)
#pragma unroll
        for (int nb = 0; nb < 4; nb++) {
            int row = dtile + m0 + mi * 16 + g;
            int col = etile + n0 + nb * 8 + tg * 2;
            *(float2*)&gp[(size_t)row * Dn + col]       = make_float2(acc[mi][nb][0], acc[mi][nb][1]);
            *(float2*)&gp[(size_t)(row + 8) * Dn + col] = make_float2(acc[mi][nb][2], acc[mi][nb][3]);
        }
}

// reduce partials + mean correction -> covariance (both triangles)
__global__ void gram_reduce() {
    int idx = blockIdx.x * 256 + threadIdx.x;
    int d = idx / Dn, e = idx % Dn;
    if (e > d) return;
    float s = 0.f;
#pragma unroll
    for (int g = 0; g < SPLIT; g++) s += g_Gpart[g][(size_t)d * Dn + e];
    float m = 0.f;
#pragma unroll
    for (int b = 0; b < Bn; b++) m += g_bmean[b][d] * g_bmean[b][e];
    s -= (float)Tn * m;
    s *= (1.0f / ((float)(Tn - 1) * (float)Bn));
    g_C[(size_t)d * Dn + e] = s;
    g_C[(size_t)e * Dn + d] = s;
}

// ---------------- 3) Cholesky, NB=64, warp-shuffle panel factor -------------
__device__ __forceinline__ void factor32_warp(float* s, int r0, int c0, int lane) {
    float a[32];
#pragma unroll
    for (int i = 0; i < 32; i++) a[i] = (i >= lane) ? s[(r0 + i) * 65 + c0 + lane] : 0.f;
#pragma unroll
    for (int j = 0; j < 32; j++) {
        float pivot = __shfl_sync(0xffffffffu, a[j], j);
        float rinv  = 1.0f / sqrtf(pivot);
        float lej = 0.f;
#pragma unroll
        for (int i = 0; i < 32; i++) {
            float lij = __shfl_sync(0xffffffffu, a[i], j) * rinv;
            if (i == lane) lej = lij;
            if (lane == j) a[i] = lij;
            else if (lane > j && i >= lane) a[i] -= lij * lej;
        }
    }
#pragma unroll
    for (int i = 0; i < 32; i++)
        if (i >= lane) s[(r0 + i) * 65 + c0 + lane] = a[i];
}

__global__ void __launch_bounds__(512) chol_panel64(int j0) {
    __shared__ float s[64 * 65];
    int tid = threadIdx.x;
    for (int l = tid; l < 64 * 64; l += 512)
        s[(l >> 6) * 65 + (l & 63)] = g_C[(size_t)(j0 + (l >> 6)) * Dn + j0 + (l & 63)];
    __syncthreads();

    if (tid < 32) factor32_warp(s, 0, 0, tid);
    __syncthreads();

    if (tid >= 32 && tid < 64) {          // TRSM A21 (rows 32..63 x L11^-T)
        int r = tid;
        float t[32];
#pragma unroll
        for (int j = 0; j < 32; j++) t[j] = s[r * 65 + j];
#pragma unroll
        for (int j = 0; j < 32; j++) {
            float v = t[j];
            for (int k = 0; k < j; k++) v -= t[k] * s[j * 65 + k];
            t[j] = v / s[j * 65 + j];
        }
#pragma unroll
        for (int j = 0; j < 32; j++) s[r * 65 + j] = t[j];
    }
    __syncthreads();

    for (int l = tid; l < 32 * 32; l += 512) {    // SYRK A22 -= A21 A21^T (lower)
        int i = 32 + (l >> 5), k = 32 + (l & 31);
        if (k <= i) {
            float acc = 0.f;
#pragma unroll
            for (int j = 0; j < 32; j++) acc += s[i * 65 + j] * s[k * 65 + j];
            s[i * 65 + k] -= acc;
        }
    }
    __syncthreads();

    if (tid < 32) factor32_warp(s, 32, 32, tid);
    __syncthreads();

    for (int l = tid; l < 64 * 64; l += 512) {    // write diag block (lower)
        int i = l >> 6, k = l & 63;
        if (k <= i) g_C[(size_t)(j0 + i) * Dn + j0 + k] = s[i * 65 + k];
    }

    int r = j0 + 64 + tid;                        // panel TRSM, one row/thread
    if (r < Dn) {
        float t[64];
#pragma unroll
        for (int j = 0; j < 64; j++) t[j] = g_C[(size_t)r * Dn + j0 + j];
#pragma unroll
        for (int j = 0; j < 64; j++) {
            float v = t[j];
            for (int k = 0; k < j; k++) v -= t[k] * s[j * 65 + k];
            t[j] = v / s[j * 65 + j];
        }
#pragma unroll
        for (int j = 0; j < 64; j++) g_C[(size_t)r * Dn + j0 + j] = t[j];
    }
}

// trailing update: C[i][k] -= P_i P_k^T, 64x64 tiles, lower only
__global__ void __launch_bounds__(256) chol_syrk64(int j0) {
    int r0 = j0 + 64;
    int i0 = r0 + blockIdx.x * 64;
    int k0 = r0 + blockIdx.y * 64;
    if (k0 > i0) return;

    __shared__ float Pi[64][65], Pk[64][65];
    int tid = threadIdx.x;
    for (int l = tid; l < 64 * 64; l += 256) {
        Pi[l >> 6][l & 63] = g_C[(size_t)(i0 + (l >> 6)) * Dn + j0 + (l & 63)];
        Pk[l >> 6][l & 63] = g_C[(size_t)(k0 + (l >> 6)) * Dn + j0 + (l & 63)];
    }
    __syncthreads();

    int tx = tid & 15, ty = tid >> 4;
    float acc[4][4] = {};
#pragma unroll 4
    for (int j = 0; j < 64; j++) {
        float pi[4], pk[4];
#pragma unroll
        for (int r = 0; r < 4; r++) pi[r] = Pi[4 * ty + r][j];
#pragma unroll
        for (int c = 0; c < 4; c++) pk[c] = Pk[4 * tx + c][j];
#pragma unroll
        for (int r = 0; r < 4; r++)
#pragma unroll
            for (int c = 0; c < 4; c++) acc[r][c] += pi[r] * pk[c];
    }
#pragma unroll
    for (int r = 0; r < 4; r++)
#pragma unroll
        for (int c = 0; c < 4; c++) {
            int gi = i0 + 4 * ty + r, gk = k0 + 4 * tx + c;
            if (gk <= gi) g_C[(size_t)gi * Dn + gk] -= acc[r][c];
        }
}

// ---------------- 4) output --------------------------------------------------
__global__ void __launch_bounds__(512) out_kernel(const float* __restrict__ z,
                                                 float* __restrict__ out) {
    int sidx = blockIdx.x;
    int d    = threadIdx.x;
    __shared__ float zs[Dn];
    zs[d] = z[(size_t)sidx * Dn + d];
    __syncthreads();
    float acc = g_gmean[d];
    const float* Crow = &g_C[(size_t)d * Dn];
    for (int e = 0; e <= d; e++) acc += zs[e] * Crow[e];
    out[(size_t)sidx * Dn + d] = acc;
}

// ---------------- launch -----------------------------------------------------
extern "C" void kernel_launch(void* const* d_in, const int* in_sizes, int n_in,
                              void* d_out, int out_size) {
    const float* x = (const float*)d_in[0];
    const float* z = (const float*)d_in[1];
    if (in_sizes[0] != Bn * Tn * Dn) { x = (const float*)d_in[1]; z = (const float*)d_in[0]; }
    float* out = (float*)d_out;

    conv_mean<<<dim3(4, Bn, SEG), 128>>>(x);
    mean_final<<<(Bn * Dn) / 256, 256>>>();
    gmean_kernel<<<1, Dn>>>();

    __nv_bfloat16* xcb;
    cudaGetSymbolAddress((void**)&xcb, g_xcb);
    gram_mma<<<dim3(4, 4, SPLIT), 256>>>(xcb);
    gram_reduce<<<(Dn * Dn) / 256, 256>>>();

    for (int p = 0; p < 8; p++) {
        int j0 = p * 64;
        chol_panel64<<<1, 512>>>(j0);
        int nt = (Dn - j0 - 64) / 64;
        if (nt > 0) chol_syrk64<<<dim3(nt, nt), 256>>>(j0);
    }

    out_kernel<<<ZB, Dn>>>(z, out);
}

// round 6
// speedup vs baseline: 1.3623x; 1.3623x over previous
#include <cuda_runtime.h>
#include <cuda_bf16.h>
#include <cstdint>
#include <math.h>

#define Bn 32
#define Tn 2048
#define Dn 512
#define ZB 32
#define SPLIT 32
#define SEG 8
#define NIT (Tn / 32)

#define NBLK 120
#define NTHR 256

// ---------------- static scratch ----------------
__device__ float g_pmean[SEG][Bn][Dn];
__device__ float g_bmean[Bn][Dn];
__device__ float g_gmean[Dn];
__device__ __nv_bfloat16 g_xcb[(size_t)Bn * Tn * Dn];
__device__ float g_Gpart[SPLIT][Dn * Dn];
__device__ float g_C[Dn * Dn];             // covariance -> L (lower triangle only)
__device__ unsigned g_barrier;

__device__ __forceinline__ uint32_t smem_u32(const void* p) {
    return (uint32_t)__cvta_generic_to_shared(p);
}

// -------- software grid barrier (all NBLK blocks co-resident) --------------
__device__ __forceinline__ void gbar(unsigned* phase) {
    __syncthreads();
    if (threadIdx.x == 0) {
        unsigned target = (++(*phase)) * NBLK;
        asm volatile("red.release.gpu.add.u32 [%0], 1;" :: "l"(&g_barrier) : "memory");
        unsigned v;
        do {
            asm volatile("ld.acquire.gpu.u32 %0, [%1];" : "=r"(v) : "l"(&g_barrier) : "memory");
        } while (v < target);
    }
    __syncthreads();
}

// ---------------- 1) fused partial means + bf16 convert ---------------------
__global__ void conv_mean(const float* __restrict__ x) {
    int b   = blockIdx.y;
    int seg = blockIdx.z;
    int d   = blockIdx.x * 128 + threadIdx.x;
    size_t base = ((size_t)b * Tn + (size_t)seg * (Tn / SEG)) * Dn + d;
    float s = 0.f;
#pragma unroll 4
    for (int t = 0; t < Tn / SEG; t++) {
        float f = x[base + (size_t)t * Dn];
        s += f;
        g_xcb[base + (size_t)t * Dn] = __float2bfloat16_rn(f);
    }
    g_pmean[seg][b][d] = s;
}

// one block, 512 threads: finish means + reset barrier
__global__ void __launch_bounds__(512) mean_fuse() {
    int d = threadIdx.x;
    if (d == 0) g_barrier = 0u;
    float gsum = 0.f;
#pragma unroll
    for (int b = 0; b < Bn; b++) {
        float s = 0.f;
#pragma unroll
        for (int g = 0; g < SEG; g++) s += g_pmean[g][b][d];
        float bm = s * (1.0f / (float)Tn);
        g_bmean[b][d] = bm;
        gsum += bm;
    }
    g_gmean[d] = gsum * (1.0f / (float)Bn);
}

// ---------------- 2) tensor-core Gram (R3, validated) -----------------------
__global__ void __launch_bounds__(256) gram_mma(const __nv_bfloat16* __restrict__ xb) {
    if (blockIdx.y > blockIdx.x) return;
    int dtile = blockIdx.x * 128;
    int etile = blockIdx.y * 128;
    int bz    = blockIdx.z;

    __shared__ __nv_bfloat16 As[2][32][128];
    __shared__ __nv_bfloat16 Bs[2][32][128];

    int tid  = threadIdx.x;
    int lane = tid & 31;
    int warp = tid >> 5;
    int m0 = (warp >> 2) * 64;
    int n0 = (warp & 3) * 32;

    const __nv_bfloat16* xbase = xb + (size_t)bz * Tn * Dn;

    float acc[4][4][4];
#pragma unroll
    for (int a = 0; a < 4; a++)
#pragma unroll
        for (int b = 0; b < 4; b++)
#pragma unroll
            for (int c = 0; c < 4; c++) acc[a][b][c] = 0.f;

    auto issue = [&](int it, int stg) {
#pragma unroll
        for (int rep = 0; rep < 2; rep++) {
            int l    = tid + rep * 256;
            int row  = l >> 4;
            int ch   = l & 15;
            int chs  = ch ^ (row & 7);
            const __nv_bfloat16* gA = xbase + (size_t)(it * 32 + row) * Dn + dtile + ch * 8;
            const __nv_bfloat16* gB = xbase + (size_t)(it * 32 + row) * Dn + etile + ch * 8;
            uint32_t sA = smem_u32(&As[stg][row][chs * 8]);
            uint32_t sB = smem_u32(&Bs[stg][row][chs * 8]);
            asm volatile("cp.async.cg.shared.global [%0], [%1], 16;" :: "r"(sA), "l"(gA));
            asm volatile("cp.async.cg.shared.global [%0], [%1], 16;" :: "r"(sB), "l"(gB));
        }
    };

    issue(0, 0);
    asm volatile("cp.async.commit_group;");

    for (int it = 0; it < NIT; it++) {
        if (it + 1 < NIT) {
            issue(it + 1, (it + 1) & 1);
            asm volatile("cp.async.commit_group;");
            asm volatile("cp.async.wait_group 1;");
        } else {
            asm volatile("cp.async.wait_group 0;");
        }
        __syncthreads();
        int stg = it & 1;

#pragma unroll
        for (int ks = 0; ks < 2; ks++) {
            uint32_t a[4][4];
            uint32_t bfr[2][4];
#pragma unroll
            for (int mi = 0; mi < 4; mi++) {
                int krow = ks * 16 + (lane & 7) + ((lane & 16) ? 8 : 0);
                int ch   = (m0 >> 3) + mi * 2 + ((lane >> 3) & 1);
                int chs  = ch ^ (krow & 7);
                uint32_t addr = smem_u32(&As[stg][krow][chs * 8]);
                asm volatile("ldmatrix.sync.aligned.m8n8.x4.trans.shared.b16 {%0,%1,%2,%3}, [%4];"
                             : "=r"(a[mi][0]), "=r"(a[mi][1]), "=r"(a[mi][2]), "=r"(a[mi][3])
                             : "r"(addr));
            }
#pragma unroll
            for (int pb = 0; pb < 2; pb++) {
                int krow = ks * 16 + (lane & 7) + ((lane & 8) ? 8 : 0);
                int ch   = (n0 >> 3) + pb * 2 + ((lane >> 4) & 1);
                int chs  = ch ^ (krow & 7);
                uint32_t addr = smem_u32(&Bs[stg][krow][chs * 8]);
                asm volatile("ldmatrix.sync.aligned.m8n8.x4.trans.shared.b16 {%0,%1,%2,%3}, [%4];"
                             : "=r"(bfr[pb][0]), "=r"(bfr[pb][1]), "=r"(bfr[pb][2]), "=r"(bfr[pb][3])
                             : "r"(addr));
            }
#pragma unroll
            for (int mi = 0; mi < 4; mi++)
#pragma unroll
                for (int nb = 0; nb < 4; nb++) {
                    uint32_t b0 = bfr[nb >> 1][(nb & 1) * 2];
                    uint32_t b1 = bfr[nb >> 1][(nb & 1) * 2 + 1];
                    asm volatile(
                        "mma.sync.aligned.m16n8k16.row.col.f32.bf16.bf16.f32 "
                        "{%0,%1,%2,%3}, {%4,%5,%6,%7}, {%8,%9}, {%0,%1,%2,%3};"
                        : "+f"(acc[mi][nb][0]), "+f"(acc[mi][nb][1]),
                          "+f"(acc[mi][nb][2]), "+f"(acc[mi][nb][3])
                        : "r"(a[mi][0]), "r"(a[mi][1]), "r"(a[mi][2]), "r"(a[mi][3]),
                          "r"(b0), "r"(b1));
                }
        }
        __syncthreads();
    }

    float* gp = g_Gpart[bz];
    int g  = lane >> 2;
    int tg = lane & 3;
#pragma unroll
    for (int mi = 0; mi < 4; mi++)
#pragma unroll
        for (int nb = 0; nb < 4; nb++) {
            int row = dtile + m0 + mi * 16 + g;
            int col = etile + n0 + nb * 8 + tg * 2;
            *(float2*)&gp[(size_t)row * Dn + col]       = make_float2(acc[mi][nb][0], acc[mi][nb][1]);
            *(float2*)&gp[(size_t)(row + 8) * Dn + col] = make_float2(acc[mi][nb][2], acc[mi][nb][3]);
        }
}

// ---------------- warp-shuffle 32x32 Cholesky factor (stride-33 smem) -------
__device__ __forceinline__ void factor32_warp(float* s, int lane) {
    float a[32];
#pragma unroll
    for (int i = 0; i < 32; i++) a[i] = (i >= lane) ? s[i * 33 + lane] : 0.f;
#pragma unroll
    for (int j = 0; j < 32; j++) {
        float pivot = __shfl_sync(0xffffffffu, a[j], j);
        float rinv  = 1.0f / sqrtf(pivot);
        float lej = 0.f;
#pragma unroll
        for (int i = 0; i < 32; i++) {
            float lij = __shfl_sync(0xffffffffu, a[i], j) * rinv;
            if (i == lane) lej = lij;
            if (lane == j) a[i] = lij;
            else if (lane > j && i >= lane) a[i] -= lij * lej;
        }
    }
#pragma unroll
    for (int i = 0; i < 32; i++)
        if (i >= lane) s[i * 33 + lane] = a[i];
}

// ---------------- 3) persistent: reduce + Cholesky + output -----------------
__global__ void __launch_bounds__(NTHR) persistent_chol(const float* __restrict__ z,
                                                        float* __restrict__ out) {
    __shared__ float sh[3 * 32 * 33];    // Pi | Pk | Dg
    float* Pi = sh;
    float* Pk = sh + 32 * 33;
    float* Dg = sh + 2 * 32 * 33;

    unsigned phase = 0;
    int bid = blockIdx.x, tid = threadIdx.x;

    // ---- phase A: gram reduce + mean correction -> g_C (lower only) ----
    for (int idx = bid * NTHR + tid; idx < Dn * Dn; idx += NBLK * NTHR) {
        int d = idx >> 9, e = idx & 511;
        if (e > d) continue;
        float s = 0.f;
#pragma unroll
        for (int g = 0; g < SPLIT; g++) s += g_Gpart[g][idx];
        float m = 0.f;
#pragma unroll
        for (int b = 0; b < Bn; b++) m += g_bmean[b][d] * g_bmean[b][e];
        g_C[idx] = (s - (float)Tn * m) * (1.0f / ((float)(Tn - 1) * (float)Bn));
    }
    gbar(&phase);

    // ---- phase B: factor diag block of panel 0 (block 0) ----
    if (bid == 0) {
        for (int l = tid; l < 1024; l += NTHR)
            Dg[(l >> 5) * 33 + (l & 31)] = g_C[(size_t)(l >> 5) * Dn + (l & 31)];
        __syncthreads();
        if (tid < 32) factor32_warp(Dg, tid);
        __syncthreads();
        for (int l = tid; l < 1024; l += NTHR) {
            int i = l >> 5, k = l & 31;
            if (k <= i) g_C[(size_t)i * Dn + k] = Dg[i * 33 + k];
        }
    }
    gbar(&phase);

    // ---- panels ----
    for (int p = 0; p < 15; p++) {
        int j0 = p * 32;
        int r0 = j0 + 32;
        int nrows = Dn - r0;

        // TRSM: one row per thread (rows r0..511), diag block in smem
        if (bid * NTHR < nrows) {
            for (int l = tid; l < 1024; l += NTHR)
                Dg[(l >> 5) * 33 + (l & 31)] = g_C[(size_t)(j0 + (l >> 5)) * Dn + j0 + (l & 31)];
            __syncthreads();
            int r = bid * NTHR + tid;
            if (r < nrows) {
                int row = r0 + r;
                float t[32];
#pragma unroll
                for (int j = 0; j < 32; j++) t[j] = g_C[(size_t)row * Dn + j0 + j];
#pragma unroll
                for (int j = 0; j < 32; j++) {
                    float v = t[j];
                    for (int k = 0; k < j; k++) v -= t[k] * Dg[j * 33 + k];
                    t[j] = v / Dg[j * 33 + j];
                }
#pragma unroll
                for (int j = 0; j < 32; j++) g_C[(size_t)row * Dn + j0 + j] = t[j];
            }
        }
        gbar(&phase);

        // SYRK trailing (32x32 tiles, lower): one tile per block.
        // ONLY the first trailing diagonal tile (ti==tk==0) is factored —
        // it is panel p+1's diagonal block and receives no further updates.
        // Other diagonal tiles get the update written back raw.
        int nt = nrows / 32;
        int ntile = nt * (nt + 1) / 2;
        if (bid < ntile) {
            int ti = 0;
            while ((ti + 1) * (ti + 2) / 2 <= bid) ti++;
            int tk = bid - ti * (ti + 1) / 2;
            int i0 = r0 + ti * 32, k0 = r0 + tk * 32;

            for (int l = tid; l < 1024; l += NTHR) {
                Pi[(l >> 5) * 33 + (l & 31)] = g_C[(size_t)(i0 + (l >> 5)) * Dn + j0 + (l & 31)];
                Pk[(l >> 5) * 33 + (l & 31)] = g_C[(size_t)(k0 + (l >> 5)) * Dn + j0 + (l & 31)];
            }
            __syncthreads();

            int i     = tid >> 3;
            int kbase = (tid & 7) * 4;
            float acc[4] = {0.f, 0.f, 0.f, 0.f};
#pragma unroll
            for (int j = 0; j < 32; j++) {
                float pi = Pi[i * 33 + j];
#pragma unroll
                for (int c = 0; c < 4; c++) acc[c] += pi * Pk[(kbase + c) * 33 + j];
            }

            if (ti != tk) {
#pragma unroll
                for (int c = 0; c < 4; c++)
                    g_C[(size_t)(i0 + i) * Dn + k0 + kbase + c] -= acc[c];
            } else if (ti == 0) {
                // next panel's diagonal: update into smem, factor, write lower
                float val[4];
#pragma unroll
                for (int c = 0; c < 4; c++)
                    val[c] = g_C[(size_t)(i0 + i) * Dn + k0 + kbase + c] - acc[c];
                __syncthreads();
#pragma unroll
                for (int c = 0; c < 4; c++) Dg[i * 33 + kbase + c] = val[c];
                __syncthreads();
                if (tid < 32) factor32_warp(Dg, tid);
                __syncthreads();
                for (int l = tid; l < 1024; l += NTHR) {
                    int ii = l >> 5, kk = l & 31;
                    if (kk <= ii) g_C[(size_t)(i0 + ii) * Dn + k0 + kk] = Dg[ii * 33 + kk];
                }
            } else {
                // later diagonal tile: just apply the update (lower part)
#pragma unroll
                for (int c = 0; c < 4; c++)
                    if (kbase + c <= i)
                        g_C[(size_t)(i0 + i) * Dn + k0 + kbase + c] -= acc[c];
            }
        }
        gbar(&phase);
    }

    // ---- output: out[s][d] = gmean[d] + sum_{e<=d} z[s][e] * L[d][e] ----
    for (int idx = bid * NTHR + tid; idx < ZB * Dn; idx += NBLK * NTHR) {
        int s = idx >> 9, d = idx & 511;
        float acc = g_gmean[d];
        const float* Crow = g_C + (size_t)d * Dn;
        const float* zr   = z + (size_t)s * Dn;
        for (int e = 0; e <= d; e++) acc += zr[e] * Crow[e];
        out[idx] = acc;
    }
}

// ---------------- launch -----------------------------------------------------
extern "C" void kernel_launch(void* const* d_in, const int* in_sizes, int n_in,
                              void* d_out, int out_size) {
    const float* x = (const float*)d_in[0];
    const float* z = (const float*)d_in[1];
    if (in_sizes[0] != Bn * Tn * Dn) { x = (const float*)d_in[1]; z = (const float*)d_in[0]; }
    float* out = (float*)d_out;

    conv_mean<<<dim3(4, Bn, SEG), 128>>>(x);
    mean_fuse<<<1, 512>>>();

    __nv_bfloat16* xcb;
    cudaGetSymbolAddress((void**)&xcb, g_xcb);
    gram_mma<<<dim3(4, 4, SPLIT), 256>>>(xcb);

    persistent_chol<<<NBLK, NTHR>>>(z, out);
}